// round 16
// baseline (speedup 1.0000x reference)
#include <cuda_runtime.h>
#include <math.h>

// VIN: B=128 images 64x64, L_I=2, L_H=150 (collapsed analytically), L_Q=10, K=50.
// Grid = 16 CTAs x 256 threads; one WARP per image (8 images/CTA).
// R10 skeleton (block-wide loads, ONE block barrier, zero redundant pre-barrier
// LDGs) + post-barrier gw = fc*q_w fold (FMAs only) and rp via shuffles.
// Fast path (w==0, verified at runtime): VI scan is identity, v never reaches
// the output -> per-image answer needs only a 5x5 X patch.
// Slow path (w!=0, uniform): full VI per image on global scratch.

#define NT    256
#define GRID  16
#define PADW  68
#define BUF   4488        // 66*68

__device__ float g_scr[GRID][3*BUF];   // slow-path scratch (never hot)

__global__ __launch_bounds__(NT, 1)
void vin_kernel(const float* __restrict__ X,
                const float* __restrict__ h_w,
                const float* __restrict__ h_b,
                const float* __restrict__ r_w,
                const float* __restrict__ q_w,
                const float* __restrict__ w,
                const float* __restrict__ fc_w,
                const void*  S1v, const void* S2v,
                const void*  kv,
                float* __restrict__ out)
{
    __shared__ float qw_s[90];            // q_w (block-wide)
    __shared__ float fc_s[80];            // fc_w (block-wide)
    __shared__ float ws[90];              // w (slow path)
    __shared__ float partial_s[152];      // W_eff partials (19 outs x 8 chunks)
    __shared__ float weff_sh[8][20];      // per-warp W_eff copy (+bias)
    __shared__ float xs_s[8][52];         // per-warp 2ch x 5x5 X patch
    __shared__ float gw_sh[8][72];        // per-warp gw[j][m] = sum_a fc[j,a]*qw[a,m]
    __shared__ int   s64_sm, kval_s;

    const int t    = threadIdx.x;
    const int warp = t >> 5;
    const int lane = t & 31;
    const int b    = blockIdx.x * 8 + warp;     // this warp's image

    // ---------- Warp-local loads: the dependent chain issues immediately ----------
    float wv0 = 0.f, wv1 = 0.f, wv2 = 0.f;
    {
        int i0 = lane * 3;
        if (i0     < 90) wv0 = w[i0];
        if (i0 + 1 < 90) wv1 = w[i0 + 1];
        if (i0 + 2 < 90) wv2 = w[i0 + 2];
    }
    // int64-vs-int32 layout probe: int64 LE => all high words zero (vals < 64).
    int hi = ((const int*)S1v)[2*lane + 1] | ((const int*)S1v)[2*(lane + 32) + 1];
    // S candidates for this warp's image, one per lane 0..3.
    int scand = 0;
    if      (lane == 0) scand = ((const int*)S1v)[b];
    else if (lane == 1) scand = (int)((const long long*)S1v)[b];
    else if (lane == 2) scand = ((const int*)S2v)[b];
    else if (lane == 3) scand = (int)((const long long*)S2v)[b];

    unsigned wb  = __ballot_sync(0xFFFFFFFFu, (wv0 != 0.f) || (wv1 != 0.f) || (wv2 != 0.f));
    unsigned pbv = __ballot_sync(0xFFFFFFFFu, hi != 0);
    const int wnz = (wb != 0u);
    const int s64 = (pbv == 0u);
    const int si  = __shfl_sync(0xFFFFFFFFu, scand, s64 ? 1 : 0);
    const int sj  = __shfl_sync(0xFFFFFFFFu, scand, s64 ? 3 : 2);

    // X patch loads (trip 2 of the dependent chain) — warp-local, pre-barrier.
    #pragma unroll
    for (int q2 = 0; q2 < 2; q2++) {
        int p = 2*lane + q2;
        if (p < 50) {
            int c = p / 25, rr = (p % 25) / 5, cc = p % 5;
            int ii = si - 2 + rr, jj = sj - 2 + cc;
            xs_s[warp][p] = (ii >= 0 && ii < 64 && jj >= 0 && jj < 64)
                          ? X[(size_t)b*8192 + c*4096 + ii*64 + jj] : 0.0f;
        }
    }

    // ---------- Block-wide small loads + W_eff partials (pre-barrier) ----------
    if (t >= 160 && t < 250) qw_s[t - 160] = q_w[t - 160];
    if (t < 80) fc_s[t] = fc_w[t];
    if (t == 255) kval_s = kv ? ((const int*)kv)[0] : 50;   // LE low word
    if (warp == 0) {               // stash w + s64 flag for slow path
        int i0 = lane * 3;
        if (i0     < 90) ws[i0]     = wv0;
        if (i0 + 1 < 90) ws[i0 + 1] = wv1;
        if (i0 + 2 < 90) ws[i0 + 2] = wv2;
        if (lane == 0) s64_sm = s64;
    }
    if (t < 152) {  // 19 outputs x 8 chunks over 150 hidden channels
        int o = t >> 3, c = t & 7;
        int h0 = c * 19, h1 = (h0 + 19 < 150) ? h0 + 19 : 150;
        float acc = 0.0f;
        if (o < 18) { for (int h = h0; h < h1; h++) acc += r_w[h] * h_w[h*18 + o]; }
        else        { for (int h = h0; h < h1; h++) acc += r_w[h] * h_b[h]; }
        partial_s[t] = acc;
    }
    __syncthreads();     // the ONLY block barrier on the fast path

    // Per-warp redundant W_eff reduce (8 smem adds per lane<19; FMAs are free).
    if (lane < 19) {
        float a = 0.0f;
        #pragma unroll
        for (int c = 0; c < 8; c++) a += partial_s[lane*8 + c];
        weff_sh[warp][lane] = a;
    }
    __syncwarp();

    if (!wnz) {
        // ================= FAST PATH (w == 0) =================
        const float* weff = weff_sh[warp];
        // rp patch (lanes 0..8) — SAME-pad zero for the q conv.
        float rp = 0.f;
        if (lane < 9) {
            int dy = lane / 3, dx = lane % 3;
            int ii = si - 1 + dy, jj = sj - 1 + dx;
            if (ii >= 0 && ii < 64 && jj >= 0 && jj < 64) {
                float acc = weff[18];
                #pragma unroll
                for (int c = 0; c < 2; c++)
                    #pragma unroll
                    for (int ky = 0; ky < 3; ky++)
                        #pragma unroll
                        for (int kx = 0; kx < 3; kx++)
                            acc += weff[c*9 + ky*3 + kx]
                                 * xs_s[warp][c*25 + (dy+ky)*5 + (dx+kx)];
                rp = acc;
            }
        }
        // gw fold (all lanes, independent of rp; post-barrier FMAs only):
        // gw[j][m] = sum_a fc[j,a]*qw[a,m], 72 entries, <=3 per lane.
        {
            const int e0 = lane, e1 = lane + 32, e2 = lane + 64;
            float g0 = 0.f, g1 = 0.f, g2 = 0.f;
            {
                int j = e0/9, m = e0 % 9;
                #pragma unroll
                for (int a = 0; a < 10; a++)
                    g0 += fc_s[j*10 + a] * qw_s[a*9 + m];
            }
            {
                int j = e1/9, m = e1 % 9;
                #pragma unroll
                for (int a = 0; a < 10; a++)
                    g1 += fc_s[j*10 + a] * qw_s[a*9 + m];
            }
            if (e2 < 72) {
                int j = e2/9, m = e2 % 9;
                #pragma unroll
                for (int a = 0; a < 10; a++)
                    g2 += fc_s[j*10 + a] * qw_s[a*9 + m];
            }
            gw_sh[warp][e0] = g0;
            gw_sh[warp][e1] = g1;
            if (e2 < 72) gw_sh[warp][e2] = g2;
        }
        __syncwarp();
        // Broadcast rp via register shuffles (no smem round trip).
        float r0 = __shfl_sync(0xFFFFFFFFu, rp, 0);
        float r1 = __shfl_sync(0xFFFFFFFFu, rp, 1);
        float r2 = __shfl_sync(0xFFFFFFFFu, rp, 2);
        float r3 = __shfl_sync(0xFFFFFFFFu, rp, 3);
        float r4 = __shfl_sync(0xFFFFFFFFu, rp, 4);
        float r5 = __shfl_sync(0xFFFFFFFFu, rp, 5);
        float r6 = __shfl_sync(0xFFFFFFFFu, rp, 6);
        float r7 = __shfl_sync(0xFFFFFFFFu, rp, 7);
        float r8 = __shfl_sync(0xFFFFFFFFu, rp, 8);
        if (lane < 8) {
            const float* gwp = gw_sh[warp] + lane*9;
            float lg = gwp[0]*r0 + gwp[1]*r1 + gwp[2]*r2
                     + gwp[3]*r3 + gwp[4]*r4 + gwp[5]*r5
                     + gwp[6]*r6 + gwp[7]*r7 + gwp[8]*r8;
            float m = lg;
            #pragma unroll
            for (int d = 4; d >= 1; d >>= 1)
                m = fmaxf(m, __shfl_xor_sync(0xFFu, m, d));
            float ex = __expf(lg - m);
            float den = ex;
            #pragma unroll
            for (int d = 4; d >= 1; d >>= 1)
                den += __shfl_xor_sync(0xFFu, den, d);
            float inv = 1.0f / den;
            out[b*8 + lane]         = lg;             // logits block
            out[128*8 + b*8 + lane] = ex * inv;       // probs block
        }
        return;
    }

    // ========== SLOW PATH (w != 0, uniform): full VI per image ==========
    float* r_s = g_scr[blockIdx.x];
    float* va  = r_s + BUF;
    float* vb  = r_s + 2*BUF;
    const float* weff0 = weff_sh[warp];   // this warp's identical copy
    const int K = kval_s;

    for (int img = 0; img < 8; img++) {
        const int b2 = blockIdx.x * 8 + img;
        for (int idx = t; idx < 3*BUF; idx += NT) r_s[idx] = 0.0f;
        __syncthreads();

        // r = conv3x3(X, W_eff) + b_eff (SAME)
        {
            const float beff = weff0[18];
            const float* X0 = X + (size_t)b2 * 8192;
            #pragma unroll 1
            for (int s = 0; s < 16; s++) {
                int p = s*NT + t;
                int i = p >> 6, j = p & 63;
                float acc = beff;
                #pragma unroll
                for (int c = 0; c < 2; c++) {
                    const float* Xc = X0 + c*4096;
                    #pragma unroll
                    for (int dy = 0; dy < 3; dy++) {
                        int ii = i + dy - 1;
                        #pragma unroll
                        for (int dx = 0; dx < 3; dx++) {
                            int jj = j + dx - 1;
                            if (ii >= 0 && ii < 64 && jj >= 0 && jj < 64)
                                acc += weff0[c*9 + dy*3 + dx] * Xc[ii*64 + jj];
                        }
                    }
                }
                r_s[(i+1)*PADW + (j+1)] = acc;
            }
        }
        __syncthreads();

        // v0 = max_a conv3x3(r, q_w[a])
        #pragma unroll 1
        for (int s = 0; s < 16; s++) {
            int p = s*NT + t;
            int i = p >> 6, j = p & 63;
            float n[9];
            #pragma unroll
            for (int dy = 0; dy < 3; dy++)
                #pragma unroll
                for (int dx = 0; dx < 3; dx++)
                    n[dy*3 + dx] = r_s[(i+dy)*PADW + (j+dx)];
            float vmax = -3.402823466e38f;
            #pragma unroll
            for (int a = 0; a < 10; a++) {
                float acc = 0.0f;
                #pragma unroll
                for (int m = 0; m < 9; m++) acc += qw_s[a*9 + m] * n[m];
                vmax = fmaxf(vmax, acc);
            }
            va[(i+1)*PADW + (j+1)] = vmax;
        }
        __syncthreads();

        // v <- max_a ( conv3x3(r, q_w[a]) + conv3x3(v, w[a]) )
        float* vcur = va;
        float* vnxt = vb;
        for (int it = 0; it < K - 1; it++) {
            #pragma unroll 1
            for (int s = 0; s < 16; s++) {
                int p = s*NT + t;
                int i = p >> 6, j = p & 63;
                float rn[9], vn[9];
                #pragma unroll
                for (int dy = 0; dy < 3; dy++)
                    #pragma unroll
                    for (int dx = 0; dx < 3; dx++) {
                        rn[dy*3 + dx] = r_s [(i+dy)*PADW + (j+dx)];
                        vn[dy*3 + dx] = vcur[(i+dy)*PADW + (j+dx)];
                    }
                float vmax = -3.402823466e38f;
                #pragma unroll
                for (int a = 0; a < 10; a++) {
                    float acc = 0.0f;
                    #pragma unroll
                    for (int m = 0; m < 9; m++)
                        acc += qw_s[a*9 + m]*rn[m] + ws[a*9 + m]*vn[m];
                    vmax = fmaxf(vmax, acc);
                }
                vnxt[(i+1)*PADW + (j+1)] = vmax;
            }
            float* tmp = vcur; vcur = vnxt; vnxt = tmp;
            __syncthreads();
        }

        if (t == 0) {
            int si2, sj2;
            if (s64_sm) {
                si2 = (int)((const long long*)S1v)[b2];
                sj2 = (int)((const long long*)S2v)[b2];
            } else {
                si2 = ((const int*)S1v)[b2];
                sj2 = ((const int*)S2v)[b2];
            }
            float qout[10];
            #pragma unroll
            for (int a = 0; a < 10; a++) {
                float acc = 0.0f;
                #pragma unroll
                for (int dy = 0; dy < 3; dy++)
                    #pragma unroll
                    for (int dx = 0; dx < 3; dx++)
                        acc += qw_s[a*9 + dy*3 + dx] * r_s [(si2+dy)*PADW + (sj2+dx)]
                             + ws  [a*9 + dy*3 + dx] * vcur[(si2+dy)*PADW + (sj2+dx)];
                qout[a] = acc;
            }
            float logits[8], lmax = -3.402823466e38f;
            #pragma unroll
            for (int j = 0; j < 8; j++) {
                float acc = 0.0f;
                #pragma unroll
                for (int a = 0; a < 10; a++) acc += qout[a] * fc_s[j*10 + a];
                logits[j] = acc;
                lmax = fmaxf(lmax, acc);
            }
            float ex[8], den = 0.0f;
            #pragma unroll
            for (int j = 0; j < 8; j++) { ex[j] = __expf(logits[j] - lmax); den += ex[j]; }
            float inv = 1.0f / den;
            #pragma unroll
            for (int j = 0; j < 8; j++) {
                out[b2*8 + j]         = logits[j];
                out[128*8 + b2*8 + j] = ex[j] * inv;
            }
        }
        __syncthreads();   // scratch reuse for next image
    }
}

extern "C" void kernel_launch(void* const* d_in, const int* in_sizes, int n_in,
                              void* d_out, int out_size)
{
    (void)in_sizes; (void)out_size;
    const float* X    = (const float*)d_in[0];
    const float* h_w  = (const float*)d_in[1];
    const float* h_b  = (const float*)d_in[2];
    const float* r_w  = (const float*)d_in[3];
    const float* q_w  = (const float*)d_in[4];
    const float* w    = (const float*)d_in[5];
    const float* fc_w = (const float*)d_in[6];
    const void*  S1   = d_in[7];
    const void*  S2   = d_in[8];
    // d_in[9], d_in[10] = O1, O2: unused by the reference computation
    const void*  kv   = (n_in > 11) ? d_in[11] : nullptr;

    vin_kernel<<<GRID, NT>>>(X, h_w, h_b, r_w, q_w, w, fc_w, S1, S2, kv,
                             (float*)d_out);
}

// round 17
// speedup vs baseline: 1.0545x; 1.0545x over previous
#include <cuda_runtime.h>
#include <math.h>

// VIN: B=128 images 64x64, L_I=2, L_H=150 (collapsed analytically), L_Q=10, K=50.
// Grid = 16 CTAs x 256 threads; one WARP per image (8 images/CTA).
// Key change vs R10: h_w is STAGED into smem with coalesced float4 loads, the
// W_eff partials are computed from smem between two cheap barriers, and the
// X patch rides in REGISTERS across the barriers (no pre-barrier STS) so the
// barriers never wait on the 2-trip dependent chain.
// Fast path (w==0, verified at runtime): VI scan is identity -> per-image
// answer needs only a 5x5 X patch. Slow path (w!=0): full VI per image.

#define NT    256
#define GRID  16
#define PADW  68
#define BUF   4488        // 66*68

__device__ float g_scr[GRID][3*BUF];   // slow-path scratch (never hot)

__global__ __launch_bounds__(NT, 1)
void vin_kernel(const float* __restrict__ X,
                const float* __restrict__ h_w,
                const float* __restrict__ h_b,
                const float* __restrict__ r_w,
                const float* __restrict__ q_w,
                const float* __restrict__ w,
                const float* __restrict__ fc_w,
                const void*  S1v, const void* S2v,
                const void*  kv,
                float* __restrict__ out)
{
    __shared__ __align__(16) float hw_s[2700];   // staged h_w
    __shared__ float rw_s[152];                  // staged r_w
    __shared__ float hb_s[152];                  // staged h_b
    __shared__ float qw_s[90];                   // q_w (block-wide)
    __shared__ float fc_s[80];                   // fc_w (block-wide)
    __shared__ float ws[90];                     // w (slow path)
    __shared__ float partial_s[152];             // W_eff partials (19 x 8)
    __shared__ float weff_sh[8][20];             // per-warp W_eff (+bias)
    __shared__ float xs_s[8][52];                // per-warp 2ch x 5x5 X patch
    __shared__ float gw_sh[8][72];               // per-warp gw[j][m]
    __shared__ int   s64_sm, kval_s;

    const int t    = threadIdx.x;
    const int warp = t >> 5;
    const int lane = t & 31;
    const int b    = blockIdx.x * 8 + warp;      // this warp's image

    // ---------- Warp-local dependent chain issues first ----------
    float wv0 = 0.f, wv1 = 0.f, wv2 = 0.f;
    {
        int i0 = lane * 3;
        if (i0     < 90) wv0 = w[i0];
        if (i0 + 1 < 90) wv1 = w[i0 + 1];
        if (i0 + 2 < 90) wv2 = w[i0 + 2];
    }
    // int64-vs-int32 layout probe: int64 LE => all high words zero (vals < 64).
    int hi = ((const int*)S1v)[2*lane + 1] | ((const int*)S1v)[2*(lane + 32) + 1];
    // S candidates for this warp's image, one per lane 0..3.
    int scand = 0;
    if      (lane == 0) scand = ((const int*)S1v)[b];
    else if (lane == 1) scand = (int)((const long long*)S1v)[b];
    else if (lane == 2) scand = ((const int*)S2v)[b];
    else if (lane == 3) scand = (int)((const long long*)S2v)[b];

    unsigned wb  = __ballot_sync(0xFFFFFFFFu, (wv0 != 0.f) || (wv1 != 0.f) || (wv2 != 0.f));
    unsigned pbv = __ballot_sync(0xFFFFFFFFu, hi != 0);
    const int wnz = (wb != 0u);
    const int s64 = (pbv == 0u);
    const int si  = __shfl_sync(0xFFFFFFFFu, scand, s64 ? 1 : 0);
    const int sj  = __shfl_sync(0xFFFFFFFFu, scand, s64 ? 3 : 2);

    // X patch loads (trip 2) — kept in REGISTERS across the barriers.
    float xa = 0.f, xb2 = 0.f;
    const int p0 = 2*lane, p1 = 2*lane + 1;
    {
        int c = p0/25, rr = (p0%25)/5, cc = p0%5;
        int ii = si - 2 + rr, jj = sj - 2 + cc;
        if (p0 < 50 && ii >= 0 && ii < 64 && jj >= 0 && jj < 64)
            xa = X[(size_t)b*8192 + c*4096 + ii*64 + jj];
    }
    {
        int c = p1/25, rr = (p1%25)/5, cc = p1%5;
        int ii = si - 2 + rr, jj = sj - 2 + cc;
        if (p1 < 50 && ii >= 0 && ii < 64 && jj >= 0 && jj < 64)
            xb2 = X[(size_t)b*8192 + c*4096 + ii*64 + jj];
    }

    // ---------- Coalesced staging of h_w / h_b / r_w + small loads ----------
    {
        const float4* src = reinterpret_cast<const float4*>(h_w);
        float4* dst = reinterpret_cast<float4*>(hw_s);
        #pragma unroll
        for (int k = 0; k < 3; k++) {
            int idx = t + k*NT;
            if (idx < 675) dst[idx] = src[idx];
        }
    }
    if (t < 150) { rw_s[t] = r_w[t]; hb_s[t] = h_b[t]; }
    if (t >= 160 && t < 250) qw_s[t - 160] = q_w[t - 160];
    if (t < 80) fc_s[t] = fc_w[t];
    if (t == 255) kval_s = kv ? ((const int*)kv)[0] : 50;   // LE low word
    if (warp == 0) {               // stash w + s64 flag for slow path
        int i0 = lane * 3;
        if (i0     < 90) ws[i0]     = wv0;
        if (i0 + 1 < 90) ws[i0 + 1] = wv1;
        if (i0 + 2 < 90) ws[i0 + 2] = wv2;
        if (lane == 0) s64_sm = s64;
    }
    __syncthreads();     // barrier 1: staging visible (cheap — coalesced loads)

    // W_eff partials from SMEM: 19 outputs x 8 chunks over 150 hidden channels.
    if (t < 152) {
        int o = t >> 3, c = t & 7;
        int h0 = c * 19, h1 = (h0 + 19 < 150) ? h0 + 19 : 150;
        float acc = 0.0f;
        if (o < 18) { for (int h = h0; h < h1; h++) acc += rw_s[h] * hw_s[h*18 + o]; }
        else        { for (int h = h0; h < h1; h++) acc += rw_s[h] * hb_s[h]; }
        partial_s[t] = acc;
    }
    __syncthreads();     // barrier 2: partials visible (pure smem, very cheap)

    // Per-warp W_eff reduce (independent of X).
    if (lane < 19) {
        float a = 0.0f;
        #pragma unroll
        for (int c = 0; c < 8; c++) a += partial_s[lane*8 + c];
        weff_sh[warp][lane] = a;
    }
    // gw fold (independent of X, hides its remaining latency):
    // gw[j][m] = sum_a fc[j,a]*qw[a,m], 72 entries, <=3 per lane.
    {
        const int e0 = lane, e1 = lane + 32, e2 = lane + 64;
        float g0 = 0.f, g1 = 0.f, g2 = 0.f;
        {
            int j = e0/9, m = e0 % 9;
            #pragma unroll
            for (int a = 0; a < 10; a++) g0 += fc_s[j*10 + a] * qw_s[a*9 + m];
        }
        {
            int j = e1/9, m = e1 % 9;
            #pragma unroll
            for (int a = 0; a < 10; a++) g1 += fc_s[j*10 + a] * qw_s[a*9 + m];
        }
        if (e2 < 72) {
            int j = e2/9, m = e2 % 9;
            #pragma unroll
            for (int a = 0; a < 10; a++) g2 += fc_s[j*10 + a] * qw_s[a*9 + m];
        }
        gw_sh[warp][e0] = g0;
        gw_sh[warp][e1] = g1;
        if (e2 < 72) gw_sh[warp][e2] = g2;
    }
    // Now publish the X patch (stalls only here, when X has mostly landed).
    if (p0 < 50) xs_s[warp][p0] = xa;
    if (p1 < 50) xs_s[warp][p1] = xb2;
    __syncwarp();

    if (!wnz) {
        // ================= FAST PATH (w == 0) =================
        const float* weff = weff_sh[warp];
        float rp = 0.f;
        if (lane < 9) {
            int dy = lane / 3, dx = lane % 3;
            int ii = si - 1 + dy, jj = sj - 1 + dx;
            if (ii >= 0 && ii < 64 && jj >= 0 && jj < 64) {   // SAME-pad zero
                float acc = weff[18];
                #pragma unroll
                for (int c = 0; c < 2; c++)
                    #pragma unroll
                    for (int ky = 0; ky < 3; ky++)
                        #pragma unroll
                        for (int kx = 0; kx < 3; kx++)
                            acc += weff[c*9 + ky*3 + kx]
                                 * xs_s[warp][c*25 + (dy+ky)*5 + (dx+kx)];
                rp = acc;
            }
        }
        // Broadcast rp via register shuffles (no smem round trip).
        float r0 = __shfl_sync(0xFFFFFFFFu, rp, 0);
        float r1 = __shfl_sync(0xFFFFFFFFu, rp, 1);
        float r2 = __shfl_sync(0xFFFFFFFFu, rp, 2);
        float r3 = __shfl_sync(0xFFFFFFFFu, rp, 3);
        float r4 = __shfl_sync(0xFFFFFFFFu, rp, 4);
        float r5 = __shfl_sync(0xFFFFFFFFu, rp, 5);
        float r6 = __shfl_sync(0xFFFFFFFFu, rp, 6);
        float r7 = __shfl_sync(0xFFFFFFFFu, rp, 7);
        float r8 = __shfl_sync(0xFFFFFFFFu, rp, 8);
        if (lane < 8) {
            const float* gwp = gw_sh[warp] + lane*9;
            float lg = gwp[0]*r0 + gwp[1]*r1 + gwp[2]*r2
                     + gwp[3]*r3 + gwp[4]*r4 + gwp[5]*r5
                     + gwp[6]*r6 + gwp[7]*r7 + gwp[8]*r8;
            float m = lg;
            #pragma unroll
            for (int d = 4; d >= 1; d >>= 1)
                m = fmaxf(m, __shfl_xor_sync(0xFFu, m, d));
            float ex = __expf(lg - m);
            float den = ex;
            #pragma unroll
            for (int d = 4; d >= 1; d >>= 1)
                den += __shfl_xor_sync(0xFFu, den, d);
            float inv = 1.0f / den;
            out[b*8 + lane]         = lg;             // logits block
            out[128*8 + b*8 + lane] = ex * inv;       // probs block
        }
        return;
    }

    // ========== SLOW PATH (w != 0, uniform): full VI per image ==========
    float* r_s = g_scr[blockIdx.x];
    float* va  = r_s + BUF;
    float* vb  = r_s + 2*BUF;
    const float* weff0 = weff_sh[warp];   // identical per-warp copies
    const int K = kval_s;

    for (int img = 0; img < 8; img++) {
        const int b2 = blockIdx.x * 8 + img;
        for (int idx = t; idx < 3*BUF; idx += NT) r_s[idx] = 0.0f;
        __syncthreads();

        // r = conv3x3(X, W_eff) + b_eff (SAME)
        {
            const float beff = weff0[18];
            const float* X0 = X + (size_t)b2 * 8192;
            #pragma unroll 1
            for (int s = 0; s < 16; s++) {
                int p = s*NT + t;
                int i = p >> 6, j = p & 63;
                float acc = beff;
                #pragma unroll
                for (int c = 0; c < 2; c++) {
                    const float* Xc = X0 + c*4096;
                    #pragma unroll
                    for (int dy = 0; dy < 3; dy++) {
                        int ii = i + dy - 1;
                        #pragma unroll
                        for (int dx = 0; dx < 3; dx++) {
                            int jj = j + dx - 1;
                            if (ii >= 0 && ii < 64 && jj >= 0 && jj < 64)
                                acc += weff0[c*9 + dy*3 + dx] * Xc[ii*64 + jj];
                        }
                    }
                }
                r_s[(i+1)*PADW + (j+1)] = acc;
            }
        }
        __syncthreads();

        // v0 = max_a conv3x3(r, q_w[a])
        #pragma unroll 1
        for (int s = 0; s < 16; s++) {
            int p = s*NT + t;
            int i = p >> 6, j = p & 63;
            float n[9];
            #pragma unroll
            for (int dy = 0; dy < 3; dy++)
                #pragma unroll
                for (int dx = 0; dx < 3; dx++)
                    n[dy*3 + dx] = r_s[(i+dy)*PADW + (j+dx)];
            float vmax = -3.402823466e38f;
            #pragma unroll
            for (int a = 0; a < 10; a++) {
                float acc = 0.0f;
                #pragma unroll
                for (int m = 0; m < 9; m++) acc += qw_s[a*9 + m] * n[m];
                vmax = fmaxf(vmax, acc);
            }
            va[(i+1)*PADW + (j+1)] = vmax;
        }
        __syncthreads();

        // v <- max_a ( conv3x3(r, q_w[a]) + conv3x3(v, w[a]) )
        float* vcur = va;
        float* vnxt = vb;
        for (int it = 0; it < K - 1; it++) {
            #pragma unroll 1
            for (int s = 0; s < 16; s++) {
                int p = s*NT + t;
                int i = p >> 6, j = p & 63;
                float rn[9], vn[9];
                #pragma unroll
                for (int dy = 0; dy < 3; dy++)
                    #pragma unroll
                    for (int dx = 0; dx < 3; dx++) {
                        rn[dy*3 + dx] = r_s [(i+dy)*PADW + (j+dx)];
                        vn[dy*3 + dx] = vcur[(i+dy)*PADW + (j+dx)];
                    }
                float vmax = -3.402823466e38f;
                #pragma unroll
                for (int a = 0; a < 10; a++) {
                    float acc = 0.0f;
                    #pragma unroll
                    for (int m = 0; m < 9; m++)
                        acc += qw_s[a*9 + m]*rn[m] + ws[a*9 + m]*vn[m];
                    vmax = fmaxf(vmax, acc);
                }
                vnxt[(i+1)*PADW + (j+1)] = vmax;
            }
            float* tmp = vcur; vcur = vnxt; vnxt = tmp;
            __syncthreads();
        }

        if (t == 0) {
            int si2, sj2;
            if (s64_sm) {
                si2 = (int)((const long long*)S1v)[b2];
                sj2 = (int)((const long long*)S2v)[b2];
            } else {
                si2 = ((const int*)S1v)[b2];
                sj2 = ((const int*)S2v)[b2];
            }
            float qout[10];
            #pragma unroll
            for (int a = 0; a < 10; a++) {
                float acc = 0.0f;
                #pragma unroll
                for (int dy = 0; dy < 3; dy++)
                    #pragma unroll
                    for (int dx = 0; dx < 3; dx++)
                        acc += qw_s[a*9 + dy*3 + dx] * r_s [(si2+dy)*PADW + (sj2+dx)]
                             + ws  [a*9 + dy*3 + dx] * vcur[(si2+dy)*PADW + (sj2+dx)];
                qout[a] = acc;
            }
            float logits[8], lmax = -3.402823466e38f;
            #pragma unroll
            for (int j = 0; j < 8; j++) {
                float acc = 0.0f;
                #pragma unroll
                for (int a = 0; a < 10; a++) acc += qout[a] * fc_s[j*10 + a];
                logits[j] = acc;
                lmax = fmaxf(lmax, acc);
            }
            float ex[8], den = 0.0f;
            #pragma unroll
            for (int j = 0; j < 8; j++) { ex[j] = __expf(logits[j] - lmax); den += ex[j]; }
            float inv = 1.0f / den;
            #pragma unroll
            for (int j = 0; j < 8; j++) {
                out[b2*8 + j]         = logits[j];
                out[128*8 + b2*8 + j] = ex[j] * inv;
            }
        }
        __syncthreads();   // scratch reuse for next image
    }
}

extern "C" void kernel_launch(void* const* d_in, const int* in_sizes, int n_in,
                              void* d_out, int out_size)
{
    (void)in_sizes; (void)out_size;
    const float* X    = (const float*)d_in[0];
    const float* h_w  = (const float*)d_in[1];
    const float* h_b  = (const float*)d_in[2];
    const float* r_w  = (const float*)d_in[3];
    const float* q_w  = (const float*)d_in[4];
    const float* w    = (const float*)d_in[5];
    const float* fc_w = (const float*)d_in[6];
    const void*  S1   = d_in[7];
    const void*  S2   = d_in[8];
    // d_in[9], d_in[10] = O1, O2: unused by the reference computation
    const void*  kv   = (n_in > 11) ? d_in[11] : nullptr;

    vin_kernel<<<GRID, NT>>>(X, h_w, h_b, r_w, q_w, w, fc_w, S1, S2, kv,
                             (float*)d_out);
}